// round 11
// baseline (speedup 1.0000x reference)
#include <cuda_runtime.h>

#define BB 8192
#define TT 256
#define FF 16
#define HH 8
#define FUT 8

typedef unsigned long long u64;

__device__ __forceinline__ float tanhm(float x) {
    float y;
    asm("tanh.approx.f32 %0, %1;" : "=f"(y) : "f"(x));
    return y;
}
__device__ __forceinline__ float sigm(float x) {
    return fmaf(0.5f, tanhm(0.5f * x), 0.5f);
}
__device__ __forceinline__ u64 ffma2(u64 a, u64 b, u64 c) {
    u64 d;
    asm("fma.rn.f32x2 %0, %1, %2, %3;" : "=l"(d) : "l"(a), "l"(b), "l"(c));
    return d;
}
__device__ __forceinline__ u64 pack2(float lo, float hi) {
    u64 r;
    asm("mov.b64 %0, {%1, %2};" : "=l"(r) : "f"(lo), "f"(hi));
    return r;
}
__device__ __forceinline__ float hsum2(u64 v) {
    float lo, hi;
    asm("mov.b64 {%0, %1}, %2;" : "=f"(lo), "=f"(hi) : "l"(v));
    return lo + hi;
}
__device__ __forceinline__ float2 unpack2(u64 v) {
    float lo, hi;
    asm("mov.b64 {%0, %1}, %2;" : "=f"(lo), "=f"(hi) : "l"(v));
    return make_float2(lo, hi);
}

// 1 element per thread (13.8 warps/SM -> 3/SMSP latency hiding).
// FFMA2 k2-paired, weights in smem, x pair-double-buffered (t+2 distance).
// __launch_bounds__(64, 6): reg cap 170 (natural footprint ~130, no spill).

__global__ __launch_bounds__(64, 6) void LSTM_91122026152229_kernel(
    const float* __restrict__ past,   // [B,T,F]
    const float* __restrict__ fut,    // [B,FUT]
    const float* __restrict__ W1, const float* __restrict__ U1, const float* __restrict__ b1,
    const float* __restrict__ W2, const float* __restrict__ U2, const float* __restrict__ b2,
    const float* __restrict__ Wd1, const float* __restrict__ bd1,
    const float* __restrict__ Wd2, const float* __restrict__ bd2,
    const float* __restrict__ Wo, const float* __restrict__ bo,
    float* __restrict__ out)          // [B,4]
{
    __shared__ ulonglong2 sW1if[8 * 8], sW1go[8 * 8];   // k2=0..7
    __shared__ ulonglong2 sU1if[4 * 8], sU1go[4 * 8];   // k2=0..3
    __shared__ ulonglong2 sW2if[4 * 8], sW2go[4 * 8];
    __shared__ ulonglong2 sU2if[4 * 8], sU2go[4 * 8];

    const int tid = threadIdx.x;

    // repack W1 (512 floats): src i = f*32 + g*8 + u
    for (int i = tid; i < 512; i += 64) {
        int f = i >> 5, r = i & 31, gg = r >> 3, uu = r & 7;
        int k2 = f >> 1, odd = f & 1;
        float v = W1[i];
        if (gg < 2)
            ((float*)sW1if)[((k2 * 8 + uu) << 2) + gg * 2 + odd] = v;
        else
            ((float*)sW1go)[((k2 * 8 + uu) << 2) + (gg - 2) * 2 + odd] = v;
    }
    // repack U1, W2, U2 (256 floats each)
    for (int i = tid; i < 256; i += 64) {
        int k = i >> 5, r = i & 31, gg = r >> 3, uu = r & 7;
        int k2 = k >> 1, odd = k & 1;
        int fo = ((k2 * 8 + uu) << 2) + ((gg & 1) * 2) + odd;
        float vU1 = U1[i], vW2 = W2[i], vU2 = U2[i];
        if (gg < 2) {
            ((float*)sU1if)[fo] = vU1;
            ((float*)sW2if)[fo] = vW2;
            ((float*)sU2if)[fo] = vU2;
        } else {
            ((float*)sU1go)[fo] = vU1;
            ((float*)sW2go)[fo] = vW2;
            ((float*)sU2go)[fo] = vU2;
        }
    }
    __syncthreads();

    const int g     = blockIdx.x * 64 + tid;
    const int e     = g >> 3;
    const int u     = g & 7;
    const int lane  = tid & 31;
    const int base8 = lane & 24;

    const float bi1 = b1[u], bf1 = b1[u + 8], bg1 = b1[u + 16], bq1 = b1[u + 24];
    const float bi2 = b2[u], bf2 = b2[u + 8], bg2 = b2[u + 16], bq2 = b2[u + 24];

    const ulonglong2* __restrict__ xp = (const ulonglong2*)(past + (size_t)e * (TT * FF));

    float h1 = 0.f, c1 = 0.f, h2 = 0.f, c2 = 0.f;
    u64 hp1[4], hp2[4];
    #pragma unroll
    for (int j = 0; j < 4; j++) { hp1[j] = 0ULL; hp2[j] = 0ULL; }

    // one LSTM timestep; c4 points at 4 ulonglong2 = 16 floats of x
    auto step = [&](const ulonglong2* c4) {
        const u64 xq[8] = { c4[0].x, c4[0].y, c4[1].x, c4[1].y,
                            c4[2].x, c4[2].y, c4[3].x, c4[3].y };

        // ---- layer 1 ----
        u64 ai = 0, af = 0, ag = 0, ao = 0;
        #pragma unroll
        for (int k2 = 0; k2 < 8; k2++) {
            const ulonglong2 wif = sW1if[k2 * 8 + u];
            const ulonglong2 wgo = sW1go[k2 * 8 + u];
            const u64 xv = xq[k2];
            ai = ffma2(xv, wif.x, ai);
            af = ffma2(xv, wif.y, af);
            ag = ffma2(xv, wgo.x, ag);
            ao = ffma2(xv, wgo.y, ao);
        }
        #pragma unroll
        for (int k2 = 0; k2 < 4; k2++) {
            const ulonglong2 wif = sU1if[k2 * 8 + u];
            const ulonglong2 wgo = sU1go[k2 * 8 + u];
            const u64 hv = hp1[k2];
            ai = ffma2(hv, wif.x, ai);
            af = ffma2(hv, wif.y, af);
            ag = ffma2(hv, wgo.x, ag);
            ao = ffma2(hv, wgo.y, ao);
        }
        {
            const float zi = hsum2(ai) + bi1;
            const float zf = hsum2(af) + bf1;
            const float zg = hsum2(ag) + bg1;
            const float zo = hsum2(ao) + bq1;
            c1 = fmaf(sigm(zf), c1, sigm(zi) * tanhm(zg));
            h1 = sigm(zo) * tanhm(c1);
        }
        #pragma unroll
        for (int k2 = 0; k2 < 4; k2++) {
            const float pa = __shfl_sync(0xffffffffu, h1, base8 + 2 * k2);
            const float pb = __shfl_sync(0xffffffffu, h1, base8 + 2 * k2 + 1);
            hp1[k2] = pack2(pa, pb);
        }

        // ---- layer 2 ----
        u64 yi = 0, yf = 0, yg = 0, yo = 0;
        #pragma unroll
        for (int k2 = 0; k2 < 4; k2++) {
            const ulonglong2 wif = sW2if[k2 * 8 + u];
            const ulonglong2 wgo = sW2go[k2 * 8 + u];
            const u64 hv = hp1[k2];
            yi = ffma2(hv, wif.x, yi);
            yf = ffma2(hv, wif.y, yf);
            yg = ffma2(hv, wgo.x, yg);
            yo = ffma2(hv, wgo.y, yo);
        }
        #pragma unroll
        for (int k2 = 0; k2 < 4; k2++) {
            const ulonglong2 wif = sU2if[k2 * 8 + u];
            const ulonglong2 wgo = sU2go[k2 * 8 + u];
            const u64 hv = hp2[k2];
            yi = ffma2(hv, wif.x, yi);
            yf = ffma2(hv, wif.y, yf);
            yg = ffma2(hv, wgo.x, yg);
            yo = ffma2(hv, wgo.y, yo);
        }
        {
            const float zi = hsum2(yi) + bi2;
            const float zf = hsum2(yf) + bf2;
            const float zg = hsum2(yg) + bg2;
            const float zo = hsum2(yo) + bq2;
            c2 = fmaf(sigm(zf), c2, sigm(zi) * tanhm(zg));
            h2 = sigm(zo) * tanhm(c2);
        }
        #pragma unroll
        for (int k2 = 0; k2 < 4; k2++) {
            const float pa = __shfl_sync(0xffffffffu, h2, base8 + 2 * k2);
            const float pb = __shfl_sync(0xffffffffu, h2, base8 + 2 * k2 + 1);
            hp2[k2] = pack2(pa, pb);
        }
    };

    // current pair buffer: x[t], x[t+1] = 8 ulonglong2
    ulonglong2 cb[8];
    #pragma unroll
    for (int j = 0; j < 8; j++) cb[j] = xp[j];

    #pragma unroll 1
    for (int t = 0; t < TT; t += 2) {
        // prefetch pair (t+2, t+3): load->use spans two timestep bodies
        const int tn = (t + 2 < TT) ? (t + 2) : t;
        ulonglong2 nb[8];
        #pragma unroll
        for (int j = 0; j < 8; j++) nb[j] = xp[tn * 4 + j];

        step(cb + 0);   // timestep t
        step(cb + 4);   // timestep t+1

        #pragma unroll
        for (int j = 0; j < 8; j++) cb[j] = nb[j];
    }

    // ---- MLP head ----
    float h2s[8];
    #pragma unroll
    for (int k2 = 0; k2 < 4; k2++) {
        const float2 p = unpack2(hp2[k2]);
        h2s[2 * k2] = p.x; h2s[2 * k2 + 1] = p.y;
    }

    float d1 = bd1[u];
    #pragma unroll
    for (int k = 0; k < 8; k++)
        d1 = fmaf(h2s[k], Wd1[k * 8 + u], d1);
    const float* __restrict__ fp = fut + (size_t)e * FUT;
    #pragma unroll
    for (int k = 0; k < 8; k++)
        d1 = fmaf(fp[k], Wd1[(8 + k) * 8 + u], d1);
    d1 = fmaxf(d1, 0.f);

    float d2 = bd2[u];
    #pragma unroll
    for (int k = 0; k < 8; k++) {
        const float d1k = __shfl_sync(0xffffffffu, d1, base8 + k);
        d2 = fmaf(d1k, Wd2[k * 8 + u], d2);
    }
    d2 = fmaxf(d2, 0.f);

    float o = (u < 4) ? bo[u] : 0.f;
    #pragma unroll
    for (int k = 0; k < 8; k++) {
        const float d2k = __shfl_sync(0xffffffffu, d2, base8 + k);
        if (u < 4) o = fmaf(d2k, Wo[k * 4 + u], o);
    }
    if (u < 4) out[(size_t)e * 4 + u] = o;
}

extern "C" void kernel_launch(void* const* d_in, const int* in_sizes, int n_in,
                              void* d_out, int out_size) {
    const float* past = (const float*)d_in[1];
    const float* fut  = (const float*)d_in[2];
    const float* W1   = (const float*)d_in[3];
    const float* U1   = (const float*)d_in[4];
    const float* b1   = (const float*)d_in[5];
    const float* W2   = (const float*)d_in[6];
    const float* U2   = (const float*)d_in[7];
    const float* b2   = (const float*)d_in[8];
    const float* Wd1  = (const float*)d_in[9];
    const float* bd1  = (const float*)d_in[10];
    const float* Wd2  = (const float*)d_in[11];
    const float* bd2  = (const float*)d_in[12];
    const float* Wo   = (const float*)d_in[13];
    const float* bo   = (const float*)d_in[14];

    // 65536 threads: 1 element per 8-thread group
    LSTM_91122026152229_kernel<<<(BB * HH) / 64, 64>>>(
        past, fut, W1, U1, b1, W2, U2, b2, Wd1, bd1, Wd2, bd2, Wo, bo,
        (float*)d_out);
}

// round 12
// speedup vs baseline: 1.4495x; 1.4495x over previous
#include <cuda_runtime.h>

#define BB 8192
#define TT 256
#define FF 16
#define HH 8
#define FUT 8

typedef unsigned long long u64;

__device__ __forceinline__ float tanhm(float x) {
    float y;
    asm("tanh.approx.f32 %0, %1;" : "=f"(y) : "f"(x));
    return y;
}
__device__ __forceinline__ float sigm(float x) {
    return fmaf(0.5f, tanhm(0.5f * x), 0.5f);
}
__device__ __forceinline__ u64 ffma2(u64 a, u64 b, u64 c) {
    u64 d;
    asm("fma.rn.f32x2 %0, %1, %2, %3;" : "=l"(d) : "l"(a), "l"(b), "l"(c));
    return d;
}
__device__ __forceinline__ u64 pack2(float lo, float hi) {
    u64 r;
    asm("mov.b64 %0, {%1, %2};" : "=l"(r) : "f"(lo), "f"(hi));
    return r;
}
__device__ __forceinline__ float hsum2(u64 v) {
    float lo, hi;
    asm("mov.b64 {%0, %1}, %2;" : "=f"(lo), "=f"(hi) : "l"(v));
    return lo + hi;
}
__device__ __forceinline__ float2 unpack2(u64 v) {
    float lo, hi;
    asm("mov.b64 {%0, %1}, %2;" : "=f"(lo), "=f"(hi) : "l"(v));
    return make_float2(lo, hi);
}

// 2 elems/thread, FFMA2, smem weights. Software-pipelined x-projection:
// xacc(t) is computed during iteration t-1, so layer1's critical path is
// only the 4 recurrent FFMA2 + activations; the 48-FFMA2 x-projection for
// t+1 is independent filler that hides activation/shfl/LDS stalls.

__global__ __launch_bounds__(64) void LSTM_91122026152229_kernel(
    const float* __restrict__ past,   // [B,T,F]
    const float* __restrict__ fut,    // [B,FUT]
    const float* __restrict__ W1, const float* __restrict__ U1, const float* __restrict__ b1,
    const float* __restrict__ W2, const float* __restrict__ U2, const float* __restrict__ b2,
    const float* __restrict__ Wd1, const float* __restrict__ bd1,
    const float* __restrict__ Wd2, const float* __restrict__ bd2,
    const float* __restrict__ Wo, const float* __restrict__ bo,
    float* __restrict__ out)          // [B,4]
{
    __shared__ ulonglong2 sW1if[8 * 8], sW1go[8 * 8];   // k2=0..7
    __shared__ ulonglong2 sU1if[4 * 8], sU1go[4 * 8];   // k2=0..3
    __shared__ ulonglong2 sW2if[4 * 8], sW2go[4 * 8];
    __shared__ ulonglong2 sU2if[4 * 8], sU2go[4 * 8];

    const int tid = threadIdx.x;

    // repack W1 (512 floats): src i = f*32 + g*8 + u
    for (int i = tid; i < 512; i += 64) {
        int f = i >> 5, r = i & 31, gg = r >> 3, uu = r & 7;
        int k2 = f >> 1, odd = f & 1;
        float v = W1[i];
        if (gg < 2)
            ((float*)sW1if)[((k2 * 8 + uu) << 2) + gg * 2 + odd] = v;
        else
            ((float*)sW1go)[((k2 * 8 + uu) << 2) + (gg - 2) * 2 + odd] = v;
    }
    // repack U1, W2, U2 (256 floats each)
    for (int i = tid; i < 256; i += 64) {
        int k = i >> 5, r = i & 31, gg = r >> 3, uu = r & 7;
        int k2 = k >> 1, odd = k & 1;
        int fo = ((k2 * 8 + uu) << 2) + ((gg & 1) * 2) + odd;
        float vU1 = U1[i], vW2 = W2[i], vU2 = U2[i];
        if (gg < 2) {
            ((float*)sU1if)[fo] = vU1;
            ((float*)sW2if)[fo] = vW2;
            ((float*)sU2if)[fo] = vU2;
        } else {
            ((float*)sU1go)[fo] = vU1;
            ((float*)sW2go)[fo] = vW2;
            ((float*)sU2go)[fo] = vU2;
        }
    }
    __syncthreads();

    const int g      = blockIdx.x * 64 + tid;
    const int group8 = g >> 3;
    const int u      = g & 7;
    const int lane   = tid & 31;
    const int base8  = lane & 24;

    const int eA = group8 * 2;
    const int eB = eA + 1;

    const float bi1 = b1[u], bf1 = b1[u + 8], bg1 = b1[u + 16], bq1 = b1[u + 24];
    const float bi2 = b2[u], bf2 = b2[u + 8], bg2 = b2[u + 16], bq2 = b2[u + 24];

    const ulonglong2* __restrict__ xpA = (const ulonglong2*)(past + (size_t)eA * (TT * FF));
    const ulonglong2* __restrict__ xpB = (const ulonglong2*)(past + (size_t)eB * (TT * FF));

    float h1A = 0.f, c1A = 0.f, h2A = 0.f, c2A = 0.f;
    float h1B = 0.f, c1B = 0.f, h2B = 0.f, c2B = 0.f;
    u64 hp1A[4], hp1B[4], hp2A[4], hp2B[4];
    #pragma unroll
    for (int j = 0; j < 4; j++) { hp1A[j] = 0ULL; hp1B[j] = 0ULL; hp2A[j] = 0ULL; hp2B[j] = 0ULL; }

    // x-projection: 16 floats of x -> 4 packed gate accumulators
    auto xproj = [&](const ulonglong2* r4, u64* acc) {
        const u64 xq[8] = { r4[0].x, r4[0].y, r4[1].x, r4[1].y,
                            r4[2].x, r4[2].y, r4[3].x, r4[3].y };
        u64 ai = 0, af = 0, ag = 0, ao = 0;
        #pragma unroll
        for (int k2 = 0; k2 < 8; k2++) {
            const ulonglong2 wif = sW1if[k2 * 8 + u];
            const ulonglong2 wgo = sW1go[k2 * 8 + u];
            const u64 xv = xq[k2];
            ai = ffma2(xv, wif.x, ai);
            af = ffma2(xv, wif.y, af);
            ag = ffma2(xv, wgo.x, ag);
            ao = ffma2(xv, wgo.y, ao);
        }
        acc[0] = ai; acc[1] = af; acc[2] = ag; acc[3] = ao;
    };

    // prologue: xacc(0) from x[0]; raw buffer holds x[1]
    ulonglong2 rawA[4], rawB[4];
    u64 xaccA[4], xaccB[4];
    {
        ulonglong2 x0A[4], x0B[4];
        #pragma unroll
        for (int j = 0; j < 4; j++) { x0A[j] = xpA[j]; x0B[j] = xpB[j]; }
        xproj(x0A, xaccA);
        xproj(x0B, xaccB);
        #pragma unroll
        for (int j = 0; j < 4; j++) { rawA[j] = xpA[4 + j]; rawB[j] = xpB[4 + j]; }
    }

    #pragma unroll 1
    for (int t = 0; t < TT; t++) {
        // loads for x[t+2] (consumed by xproj in the NEXT iteration)
        const int tn = (t + 2 < TT) ? (t + 2) : (TT - 1);
        const ulonglong2 nA0 = xpA[tn * 4 + 0];
        const ulonglong2 nA1 = xpA[tn * 4 + 1];
        const ulonglong2 nA2 = xpA[tn * 4 + 2];
        const ulonglong2 nA3 = xpA[tn * 4 + 3];
        const ulonglong2 nB0 = xpB[tn * 4 + 0];
        const ulonglong2 nB1 = xpB[tn * 4 + 1];
        const ulonglong2 nB2 = xpB[tn * 4 + 2];
        const ulonglong2 nB3 = xpB[tn * 4 + 3];

        // ---- phase 1: layer 1 from carried xacc + recurrent terms ----
        u64 aiA = xaccA[0], afA = xaccA[1], agA = xaccA[2], aoA = xaccA[3];
        u64 aiB = xaccB[0], afB = xaccB[1], agB = xaccB[2], aoB = xaccB[3];
        #pragma unroll
        for (int k2 = 0; k2 < 4; k2++) {
            const ulonglong2 wif = sU1if[k2 * 8 + u];
            const ulonglong2 wgo = sU1go[k2 * 8 + u];
            const u64 hA = hp1A[k2], hB = hp1B[k2];
            aiA = ffma2(hA, wif.x, aiA);  aiB = ffma2(hB, wif.x, aiB);
            afA = ffma2(hA, wif.y, afA);  afB = ffma2(hB, wif.y, afB);
            agA = ffma2(hA, wgo.x, agA);  agB = ffma2(hB, wgo.x, agB);
            aoA = ffma2(hA, wgo.y, aoA);  aoB = ffma2(hB, wgo.y, aoB);
        }
        {
            const float ziA = hsum2(aiA) + bi1, zfA = hsum2(afA) + bf1;
            const float zgA = hsum2(agA) + bg1, zoA = hsum2(aoA) + bq1;
            c1A = fmaf(sigm(zfA), c1A, sigm(ziA) * tanhm(zgA));
            h1A = sigm(zoA) * tanhm(c1A);
            const float ziB = hsum2(aiB) + bi1, zfB = hsum2(afB) + bf1;
            const float zgB = hsum2(agB) + bg1, zoB = hsum2(aoB) + bq1;
            c1B = fmaf(sigm(zfB), c1B, sigm(ziB) * tanhm(zgB));
            h1B = sigm(zoB) * tanhm(c1B);
        }
        #pragma unroll
        for (int k2 = 0; k2 < 4; k2++) {
            const float aA = __shfl_sync(0xffffffffu, h1A, base8 + 2 * k2);
            const float bA = __shfl_sync(0xffffffffu, h1A, base8 + 2 * k2 + 1);
            const float aB = __shfl_sync(0xffffffffu, h1B, base8 + 2 * k2);
            const float bB = __shfl_sync(0xffffffffu, h1B, base8 + 2 * k2 + 1);
            hp1A[k2] = pack2(aA, bA);
            hp1B[k2] = pack2(aB, bB);
        }

        // ---- phase 2 (independent filler): x-projection for t+1 ----
        u64 nxA[4], nxB[4];
        xproj(rawA, nxA);
        xproj(rawB, nxB);

        // ---- phase 3: layer 2 ----
        u64 yiA = 0, yfA = 0, ygA = 0, yoA = 0;
        u64 yiB = 0, yfB = 0, ygB = 0, yoB = 0;
        #pragma unroll
        for (int k2 = 0; k2 < 4; k2++) {
            const ulonglong2 wif = sW2if[k2 * 8 + u];
            const ulonglong2 wgo = sW2go[k2 * 8 + u];
            const u64 hA = hp1A[k2], hB = hp1B[k2];
            yiA = ffma2(hA, wif.x, yiA);  yiB = ffma2(hB, wif.x, yiB);
            yfA = ffma2(hA, wif.y, yfA);  yfB = ffma2(hB, wif.y, yfB);
            ygA = ffma2(hA, wgo.x, ygA);  ygB = ffma2(hB, wgo.x, ygB);
            yoA = ffma2(hA, wgo.y, yoA);  yoB = ffma2(hB, wgo.y, yoB);
        }
        #pragma unroll
        for (int k2 = 0; k2 < 4; k2++) {
            const ulonglong2 wif = sU2if[k2 * 8 + u];
            const ulonglong2 wgo = sU2go[k2 * 8 + u];
            const u64 hA = hp2A[k2], hB = hp2B[k2];
            yiA = ffma2(hA, wif.x, yiA);  yiB = ffma2(hB, wif.x, yiB);
            yfA = ffma2(hA, wif.y, yfA);  yfB = ffma2(hB, wif.y, yfB);
            ygA = ffma2(hA, wgo.x, ygA);  ygB = ffma2(hB, wgo.x, ygB);
            yoA = ffma2(hA, wgo.y, yoA);  yoB = ffma2(hB, wgo.y, yoB);
        }
        {
            const float ziA = hsum2(yiA) + bi2, zfA = hsum2(yfA) + bf2;
            const float zgA = hsum2(ygA) + bg2, zoA = hsum2(yoA) + bq2;
            c2A = fmaf(sigm(zfA), c2A, sigm(ziA) * tanhm(zgA));
            h2A = sigm(zoA) * tanhm(c2A);
            const float ziB = hsum2(yiB) + bi2, zfB = hsum2(yfB) + bf2;
            const float zgB = hsum2(ygB) + bg2, zoB = hsum2(yoB) + bq2;
            c2B = fmaf(sigm(zfB), c2B, sigm(ziB) * tanhm(zgB));
            h2B = sigm(zoB) * tanhm(c2B);
        }
        #pragma unroll
        for (int k2 = 0; k2 < 4; k2++) {
            const float aA = __shfl_sync(0xffffffffu, h2A, base8 + 2 * k2);
            const float bA = __shfl_sync(0xffffffffu, h2A, base8 + 2 * k2 + 1);
            const float aB = __shfl_sync(0xffffffffu, h2B, base8 + 2 * k2);
            const float bB = __shfl_sync(0xffffffffu, h2B, base8 + 2 * k2 + 1);
            hp2A[k2] = pack2(aA, bA);
            hp2B[k2] = pack2(aB, bB);
        }

        // rotate pipeline state
        #pragma unroll
        for (int j = 0; j < 4; j++) { xaccA[j] = nxA[j]; xaccB[j] = nxB[j]; }
        rawA[0] = nA0; rawA[1] = nA1; rawA[2] = nA2; rawA[3] = nA3;
        rawB[0] = nB0; rawB[1] = nB1; rawB[2] = nB2; rawB[3] = nB3;
    }

    // ---- MLP head for both elements ----
    float h2sA[8], h2sB[8];
    #pragma unroll
    for (int k2 = 0; k2 < 4; k2++) {
        const float2 pA = unpack2(hp2A[k2]);
        const float2 pB = unpack2(hp2B[k2]);
        h2sA[2 * k2] = pA.x; h2sA[2 * k2 + 1] = pA.y;
        h2sB[2 * k2] = pB.x; h2sB[2 * k2 + 1] = pB.y;
    }

    float d1A = bd1[u], d1B = d1A;
    #pragma unroll
    for (int k = 0; k < 8; k++) {
        const float wk = Wd1[k * 8 + u];
        d1A = fmaf(h2sA[k], wk, d1A);
        d1B = fmaf(h2sB[k], wk, d1B);
    }
    const float* __restrict__ fpA = fut + (size_t)eA * FUT;
    const float* __restrict__ fpB = fut + (size_t)eB * FUT;
    #pragma unroll
    for (int k = 0; k < 8; k++) {
        const float wk = Wd1[(8 + k) * 8 + u];
        d1A = fmaf(fpA[k], wk, d1A);
        d1B = fmaf(fpB[k], wk, d1B);
    }
    d1A = fmaxf(d1A, 0.f);
    d1B = fmaxf(d1B, 0.f);

    float d2A = bd2[u], d2B = d2A;
    #pragma unroll
    for (int k = 0; k < 8; k++) {
        const float wk = Wd2[k * 8 + u];
        const float d1kA = __shfl_sync(0xffffffffu, d1A, base8 + k);
        const float d1kB = __shfl_sync(0xffffffffu, d1B, base8 + k);
        d2A = fmaf(d1kA, wk, d2A);
        d2B = fmaf(d1kB, wk, d2B);
    }
    d2A = fmaxf(d2A, 0.f);
    d2B = fmaxf(d2B, 0.f);

    float oA = (u < 4) ? bo[u] : 0.f;
    float oB = oA;
    #pragma unroll
    for (int k = 0; k < 8; k++) {
        const float wk = (u < 4) ? Wo[k * 4 + u] : 0.f;
        const float d2kA = __shfl_sync(0xffffffffu, d2A, base8 + k);
        const float d2kB = __shfl_sync(0xffffffffu, d2B, base8 + k);
        oA = fmaf(d2kA, wk, oA);
        oB = fmaf(d2kB, wk, oB);
    }
    if (u < 4) {
        out[(size_t)eA * 4 + u] = oA;
        out[(size_t)eB * 4 + u] = oB;
    }
}

extern "C" void kernel_launch(void* const* d_in, const int* in_sizes, int n_in,
                              void* d_out, int out_size) {
    const float* past = (const float*)d_in[1];
    const float* fut  = (const float*)d_in[2];
    const float* W1   = (const float*)d_in[3];
    const float* U1   = (const float*)d_in[4];
    const float* b1   = (const float*)d_in[5];
    const float* W2   = (const float*)d_in[6];
    const float* U2   = (const float*)d_in[7];
    const float* b2   = (const float*)d_in[8];
    const float* Wd1  = (const float*)d_in[9];
    const float* bd1  = (const float*)d_in[10];
    const float* Wd2  = (const float*)d_in[11];
    const float* bd2  = (const float*)d_in[12];
    const float* Wo   = (const float*)d_in[13];
    const float* bo   = (const float*)d_in[14];

    // 32768 threads: 2 elements per thread, single wave (512 blocks)
    LSTM_91122026152229_kernel<<<(BB * HH / 2) / 64, 64>>>(
        past, fut, W1, U1, b1, W2, U2, b2, Wd1, bd1, Wd2, bd2, Wo, bo,
        (float*)d_out);
}